// round 15
// baseline (speedup 1.0000x reference)
#include <cuda_runtime.h>
#include <cstdint>

#define Bn 16
#define Cn 256
#define Ln 4096
#define Pn 100
#define Qn 20
#define TL 64
#define SROW 260                 // word stride of Xe/Xo rows (1040B, 16B-aligned)
#define NW 16                    // warps per block
#define KP 7                     // p per warp: p = 7w + k (100..111 zero-padded)
#define PPAD (NW * KP)           // 112
#define NTILES (Bn * (Ln / TL))  // 1024
#define GRID 148
#define NTHR (NW * 32)           // 512
#define XO_OFF (32 * SROW + 16)  // Xo base: +16 words -> odd-lane STS banks disjoint

__global__ void zero_cdf_kernel(float* out) {
    int i = blockIdx.x * 256 + threadIdx.x;
    if (i < Bn * Pn * Qn) out[i] = 0.0f;
}

__device__ __forceinline__ unsigned long long ffma2(unsigned long long a,
                                                    unsigned long long b,
                                                    unsigned long long c) {
    unsigned long long d;
    asm("fma.rn.f32x2 %0, %1, %2, %3;" : "=l"(d) : "l"(a), "l"(b), "l"(c));
    return d;
}
__device__ __forceinline__ void unpack2(unsigned long long v, float& x, float& y) {
    asm("mov.b64 {%0,%1}, %2;" : "=f"(x), "=f"(y) : "l"(v));
}
// Streaming (evict-first) 8-byte store: keeps the 524MB one-touch set stream
// from thrashing L2 / paying write-allocate.
__device__ __forceinline__ void stg_cs_f2(float2* p, float x, float y) {
    asm volatile("st.global.cs.v2.f32 [%0], {%1,%2};" :: "l"(p), "f"(x), "f"(y) : "memory");
}

// item = (cc, h): warp loads c = 4cc..4cc+3 for l = 32h + lane.  item in [0,128)
__device__ __forceinline__ float4 load_item(const float* Xb, int lane, int item) {
    int cc = item >> 1, h = item & 1;
    const float* s = Xb + (size_t)(4 * cc) * Ln + 32 * h + lane;
    float4 v;
    v.x = __ldcs(s);
    v.y = __ldcs(s + Ln);
    v.z = __ldcs(s + 2 * Ln);
    v.w = __ldcs(s + 3 * Ln);
    return v;
}
// STS.128, conflict-free per 8-lane phase (evens->Xe banks {0..15}+c0, odds->Xo {16..31}+c0)
__device__ __forceinline__ void stage_item(float* Xe, int lane, int item, float4 v) {
    int cc = item >> 1, h = item & 1;
    int r = 16 * h + (lane >> 1);
    float* base = Xe + ((lane & 1) ? XO_OFF : 0) + r * SROW + 4 * cc;
    *(float4*)base = v;
}

__global__ __launch_bounds__(NTHR, 1)
void csf_persistent_kernel(const float* __restrict__ X,
                           const float* __restrict__ proj,
                           const float* __restrict__ minv,
                           const float* __restrict__ maxv,
                           float* __restrict__ out) {
    extern __shared__ float sm[];
    float* Xe  = sm;                         // rows: l=2r; Xo at +XO_OFF: l=2r+1
    float* pst = sm + XO_OFF + 32 * SROW;    // [PPAD][Cn], rows >= Pn zero
    float* thr = pst + PPAD * Cn;            // [Pn*Qn]

    const int tid  = threadIdx.x;
    const int w    = tid >> 5;
    const int lane = tid & 31;

    // ---- One-time staging: projections (zero-pad) + thresholds ----
    {
        const int total4 = PPAD * Cn / 4;    // 7168
        const int lim4   = Pn * Cn / 4;      // 6400
        for (int i = tid; i < total4; i += NTHR) {
            float4 v = make_float4(0.f, 0.f, 0.f, 0.f);
            if (i < lim4) v = ((const float4*)proj)[i];
            ((float4*)pst)[i] = v;
        }
        for (int i = tid; i < Pn * Qn; i += NTHR) {
            int p = i / Qn, q = i % Qn;
            float f = (float)(q + 1) / (float)(Qn + 1);
            thr[i] = minv[p] + (maxv[p] - minv[p]) * f;
        }
    }

    const int pbase = KP * w;
    const float* psb = pst + pbase * Cn;
    const float* xa = Xe + lane * SROW;            // l = l0 + 2*lane
    const float* xb = Xe + XO_OFF + lane * SROW;   // l = l0 + 2*lane + 1

    int t = blockIdx.x;
    if (t >= NTILES) return;

    // Prologue: stage first tile (128 items = 8 rounds x 16 warps, exact).
    {
        const float* Xb = X + (size_t)(t >> 6) * Cn * Ln + (t & 63) * TL;
        #pragma unroll
        for (int j = 0; j < 8; j++)
            stage_item(Xe, lane, j * NW + w, load_item(Xb, lane, j * NW + w));
    }
    __syncthreads();

    while (true) {
        const int b  = t >> 6;
        const int l0 = (t & 63) * TL;

        // ---- Compute: warp w owns p = 7w..7w+6 (padded rows are zeros) ----
        unsigned long long acc0[KP], acc1[KP];
        #pragma unroll
        for (int k = 0; k < KP; k++) { acc0[k] = 0ull; acc1[k] = 0ull; }

        #pragma unroll 2
        for (int c = 0; c < Cn; c += 8) {
            ulonglong2 x0a = *(const ulonglong2*)(xa + c);
            ulonglong2 x0b = *(const ulonglong2*)(xa + c + 4);
            ulonglong2 x1a = *(const ulonglong2*)(xb + c);
            ulonglong2 x1b = *(const ulonglong2*)(xb + c + 4);
            #pragma unroll
            for (int k = 0; k < KP; k++) {
                ulonglong2 pva = *(const ulonglong2*)(psb + k * Cn + c);      // broadcast
                ulonglong2 pvb = *(const ulonglong2*)(psb + k * Cn + c + 4);  // broadcast
                acc0[k] = ffma2(pva.x, x0a.x, acc0[k]);
                acc0[k] = ffma2(pva.y, x0a.y, acc0[k]);
                acc0[k] = ffma2(pvb.x, x0b.x, acc0[k]);
                acc0[k] = ffma2(pvb.y, x0b.y, acc0[k]);
                acc1[k] = ffma2(pva.x, x1a.x, acc1[k]);
                acc1[k] = ffma2(pva.y, x1a.y, acc1[k]);
                acc1[k] = ffma2(pvb.x, x1b.x, acc1[k]);
                acc1[k] = ffma2(pvb.y, x1b.y, acc1[k]);
            }
        }

        // ---- Prefetch ENTIRE next tile into registers (hidden by epilogue) ----
        const int tn = t + GRID;
        const bool have = (tn < NTILES);
        float4 pf[8];
        if (have) {
            const float* Xb2 = X + (size_t)(tn >> 6) * Cn * Ln + (tn & 63) * TL;
            #pragma unroll
            for (int j = 0; j < 8; j++)
                pf[j] = load_item(Xb2, lane, j * NW + w);
        }

        // ---- Epilogue: streaming set stores + cdf counts ----
        float* cdfb = out + b * (Pn * Qn);
        float* setb = out + Bn * Pn * Qn + (size_t)b * Pn * Qn * Ln;

        #pragma unroll
        for (int k = 0; k < KP; k++) {
            const int p = pbase + k;
            if (p >= Pn) break;   // uniform within warp
            float e0, o0, e1, o1;
            unpack2(acc0[k], e0, o0);
            unpack2(acc1[k], e1, o1);
            float a0 = e0 + o0;   // l = l0 + 2*lane
            float a1 = e1 + o1;   // l = l0 + 2*lane + 1

            float2* dst = (float2*)(setb + (size_t)p * Qn * Ln + l0) + lane;
            const float* th = thr + p * Qn;

            #pragma unroll
            for (int qq = 0; qq < Qn; qq += 4) {
                unsigned packed = 0;
                #pragma unroll
                for (int j = 0; j < 4; j++) {
                    float tt = th[qq + j];
                    bool c0 = (a0 < tt);
                    bool c1 = (a1 < tt);
                    float f0 = c0 ? 1.0f : 0.0f;
                    float f1 = c1 ? 1.0f : 0.0f;
                    stg_cs_f2(dst + (size_t)(qq + j) * (Ln / 2), f0, f1);
                    unsigned cnt = (c0 ? 1u : 0u) + (c1 ? 1u : 0u);
                    packed += cnt << (8 * j);          // per-byte sum <= 64
                }
                unsigned r = __reduce_add_sync(0xffffffffu, packed);
                if (lane < 4) {
                    float v = (float)((r >> (8 * lane)) & 255u) * (1.0f / 4096.0f);
                    atomicAdd(cdfb + p * Qn + qq + lane, v);   // exact dyadic
                }
            }
        }

        if (!have) break;

        __syncthreads();   // all warps done reading Xe/Xo
        #pragma unroll
        for (int j = 0; j < 8; j++)
            stage_item(Xe, lane, j * NW + w, pf[j]);
        __syncthreads();   // tile ready

        t = tn;
    }
}

extern "C" void kernel_launch(void* const* d_in, const int* in_sizes, int n_in,
                              void* d_out, int out_size) {
    const float* X    = (const float*)d_in[0];
    const float* proj = (const float*)d_in[1];
    const float* minv = (const float*)d_in[2];
    const float* maxv = (const float*)d_in[3];
    float* out = (float*)d_out;

    zero_cdf_kernel<<<(Bn * Pn * Qn + 255) / 256, 256>>>(out);

    const int smem = (XO_OFF + 32 * SROW + PPAD * Cn + Pn * Qn) * (int)sizeof(float);
    cudaFuncSetAttribute(csf_persistent_kernel,
                         cudaFuncAttributeMaxDynamicSharedMemorySize, smem);
    csf_persistent_kernel<<<GRID, NTHR, smem>>>(X, proj, minv, maxv, out);
}

// round 16
// speedup vs baseline: 1.5559x; 1.5559x over previous
#include <cuda_runtime.h>
#include <cstdint>

#define Bn 16
#define Cn 256
#define Ln 4096
#define Pn 100
#define Qn 20
#define TL 64
#define SROW 260                 // word stride of Xe/Xo rows (1040B, 16B-aligned)
#define NW 16                    // warps per block
#define KP 7                     // p per warp: p = 7w + k (100..111 zero-padded)
#define PPAD (NW * KP)           // 112
#define NTILES (Bn * (Ln / TL))  // 1024
#define GRID 148
#define NTHR (NW * 32)           // 512
#define XO_OFF (32 * SROW + 16)  // Xo base: +16 words -> odd-lane STS banks disjoint

__global__ void zero_cdf_kernel(float* out) {
    int i = blockIdx.x * 256 + threadIdx.x;
    if (i < Bn * Pn * Qn) out[i] = 0.0f;
}

__device__ __forceinline__ unsigned long long ffma2(unsigned long long a,
                                                    unsigned long long b,
                                                    unsigned long long c) {
    unsigned long long d;
    asm("fma.rn.f32x2 %0, %1, %2, %3;" : "=l"(d) : "l"(a), "l"(b), "l"(c));
    return d;
}
__device__ __forceinline__ void unpack2(unsigned long long v, float& x, float& y) {
    asm("mov.b64 {%0,%1}, %2;" : "=f"(x), "=f"(y) : "l"(v));
}
// Streaming (evict-first) 8-byte store: keeps the 524MB one-touch set stream
// from thrashing L2 / paying write-allocate.
__device__ __forceinline__ void stg_cs_f2(float2* p, float x, float y) {
    asm volatile("st.global.cs.v2.f32 [%0], {%1,%2};" :: "l"(p), "f"(x), "f"(y) : "memory");
}

// item = (cc, h): warp loads c = 4cc..4cc+3 for l = 32h + lane.  item in [0,128)
__device__ __forceinline__ float4 load_item(const float* Xb, int lane, int item) {
    int cc = item >> 1, h = item & 1;
    const float* s = Xb + (size_t)(4 * cc) * Ln + 32 * h + lane;
    float4 v;
    v.x = __ldcs(s);
    v.y = __ldcs(s + Ln);
    v.z = __ldcs(s + 2 * Ln);
    v.w = __ldcs(s + 3 * Ln);
    return v;
}
// STS.128, conflict-free per 8-lane phase (evens->Xe banks {0..15}+c0, odds->Xo {16..31}+c0)
__device__ __forceinline__ void stage_item(float* Xe, int lane, int item, float4 v) {
    int cc = item >> 1, h = item & 1;
    int r = 16 * h + (lane >> 1);
    float* base = Xe + ((lane & 1) ? XO_OFF : 0) + r * SROW + 4 * cc;
    *(float4*)base = v;
}

__global__ __launch_bounds__(NTHR, 1)
void csf_persistent_kernel(const float* __restrict__ X,
                           const float* __restrict__ proj,
                           const float* __restrict__ minv,
                           const float* __restrict__ maxv,
                           float* __restrict__ out) {
    extern __shared__ float sm[];
    float* Xe  = sm;                         // rows: l=2r; Xo at +XO_OFF: l=2r+1
    float* pst = sm + XO_OFF + 32 * SROW;    // [PPAD][Cn], rows >= Pn zero
    float* thr = pst + PPAD * Cn;            // [Pn*Qn]

    const int tid  = threadIdx.x;
    const int w    = tid >> 5;
    const int lane = tid & 31;

    // ---- One-time staging: projections (zero-pad) + thresholds ----
    {
        const int total4 = PPAD * Cn / 4;    // 7168
        const int lim4   = Pn * Cn / 4;      // 6400
        for (int i = tid; i < total4; i += NTHR) {
            float4 v = make_float4(0.f, 0.f, 0.f, 0.f);
            if (i < lim4) v = ((const float4*)proj)[i];
            ((float4*)pst)[i] = v;
        }
        for (int i = tid; i < Pn * Qn; i += NTHR) {
            int p = i / Qn, q = i % Qn;
            float f = (float)(q + 1) / (float)(Qn + 1);
            thr[i] = minv[p] + (maxv[p] - minv[p]) * f;
        }
    }

    const int pbase = KP * w;
    const float* psb = pst + pbase * Cn;
    const float* xa = Xe + lane * SROW;            // l = l0 + 2*lane
    const float* xb = Xe + XO_OFF + lane * SROW;   // l = l0 + 2*lane + 1

    int t = blockIdx.x;
    if (t >= NTILES) return;

    // Prologue: stage first tile (128 items = 8 rounds x 16 warps, exact).
    {
        const float* Xb = X + (size_t)(t >> 6) * Cn * Ln + (t & 63) * TL;
        #pragma unroll
        for (int j = 0; j < 8; j++)
            stage_item(Xe, lane, j * NW + w, load_item(Xb, lane, j * NW + w));
    }
    __syncthreads();

    while (true) {
        const int b  = t >> 6;
        const int l0 = (t & 63) * TL;

        // ---- Compute: warp w owns p = 7w..7w+6 (padded rows are zeros) ----
        unsigned long long acc0[KP], acc1[KP];
        #pragma unroll
        for (int k = 0; k < KP; k++) { acc0[k] = 0ull; acc1[k] = 0ull; }

        #pragma unroll 2
        for (int c = 0; c < Cn; c += 8) {
            ulonglong2 x0a = *(const ulonglong2*)(xa + c);
            ulonglong2 x0b = *(const ulonglong2*)(xa + c + 4);
            ulonglong2 x1a = *(const ulonglong2*)(xb + c);
            ulonglong2 x1b = *(const ulonglong2*)(xb + c + 4);
            #pragma unroll
            for (int k = 0; k < KP; k++) {
                ulonglong2 pva = *(const ulonglong2*)(psb + k * Cn + c);      // broadcast
                ulonglong2 pvb = *(const ulonglong2*)(psb + k * Cn + c + 4);  // broadcast
                acc0[k] = ffma2(pva.x, x0a.x, acc0[k]);
                acc0[k] = ffma2(pva.y, x0a.y, acc0[k]);
                acc0[k] = ffma2(pvb.x, x0b.x, acc0[k]);
                acc0[k] = ffma2(pvb.y, x0b.y, acc0[k]);
                acc1[k] = ffma2(pva.x, x1a.x, acc1[k]);
                acc1[k] = ffma2(pva.y, x1a.y, acc1[k]);
                acc1[k] = ffma2(pvb.x, x1b.x, acc1[k]);
                acc1[k] = ffma2(pvb.y, x1b.y, acc1[k]);
            }
        }

        // ---- Prefetch ENTIRE next tile into registers (hidden by epilogue) ----
        const int tn = t + GRID;
        const bool have = (tn < NTILES);
        float4 pf[8];
        if (have) {
            const float* Xb2 = X + (size_t)(tn >> 6) * Cn * Ln + (tn & 63) * TL;
            #pragma unroll
            for (int j = 0; j < 8; j++)
                pf[j] = load_item(Xb2, lane, j * NW + w);
        }

        // ---- Epilogue: streaming set stores + cdf counts ----
        float* cdfb = out + b * (Pn * Qn);
        float* setb = out + Bn * Pn * Qn + (size_t)b * Pn * Qn * Ln;

        #pragma unroll
        for (int k = 0; k < KP; k++) {
            const int p = pbase + k;
            if (p >= Pn) break;   // uniform within warp
            float e0, o0, e1, o1;
            unpack2(acc0[k], e0, o0);
            unpack2(acc1[k], e1, o1);
            float a0 = e0 + o0;   // l = l0 + 2*lane
            float a1 = e1 + o1;   // l = l0 + 2*lane + 1

            float2* dst = (float2*)(setb + (size_t)p * Qn * Ln + l0) + lane;
            const float* th = thr + p * Qn;

            #pragma unroll
            for (int qq = 0; qq < Qn; qq += 4) {
                unsigned packed = 0;
                #pragma unroll
                for (int j = 0; j < 4; j++) {
                    float tt = th[qq + j];
                    bool c0 = (a0 < tt);
                    bool c1 = (a1 < tt);
                    float f0 = c0 ? 1.0f : 0.0f;
                    float f1 = c1 ? 1.0f : 0.0f;
                    stg_cs_f2(dst + (size_t)(qq + j) * (Ln / 2), f0, f1);
                    unsigned cnt = (c0 ? 1u : 0u) + (c1 ? 1u : 0u);
                    packed += cnt << (8 * j);          // per-byte sum <= 64
                }
                unsigned r = __reduce_add_sync(0xffffffffu, packed);
                if (lane < 4) {
                    float v = (float)((r >> (8 * lane)) & 255u) * (1.0f / 4096.0f);
                    atomicAdd(cdfb + p * Qn + qq + lane, v);   // exact dyadic
                }
            }
        }

        if (!have) break;

        __syncthreads();   // all warps done reading Xe/Xo
        #pragma unroll
        for (int j = 0; j < 8; j++)
            stage_item(Xe, lane, j * NW + w, pf[j]);
        __syncthreads();   // tile ready

        t = tn;
    }
}

extern "C" void kernel_launch(void* const* d_in, const int* in_sizes, int n_in,
                              void* d_out, int out_size) {
    const float* X    = (const float*)d_in[0];
    const float* proj = (const float*)d_in[1];
    const float* minv = (const float*)d_in[2];
    const float* maxv = (const float*)d_in[3];
    float* out = (float*)d_out;

    zero_cdf_kernel<<<(Bn * Pn * Qn + 255) / 256, 256>>>(out);

    const int smem = (XO_OFF + 32 * SROW + PPAD * Cn + Pn * Qn) * (int)sizeof(float);
    cudaFuncSetAttribute(csf_persistent_kernel,
                         cudaFuncAttributeMaxDynamicSharedMemorySize, smem);
    csf_persistent_kernel<<<GRID, NTHR, smem>>>(X, proj, minv, maxv, out);
}

// round 17
// speedup vs baseline: 1.6749x; 1.0765x over previous
#include <cuda_runtime.h>
#include <cstdint>

#define Bn 16
#define Cn 256
#define Ln 4096
#define Pn 100
#define Qn 20
#define TL 64
#define SROW 260                 // word stride of Xe/Xo rows (1040B, 16B-aligned)
#define NW 32                    // warps per block (split-K pairs: w <-> w+16)
#define KP 7                     // p per pair: p = 7*(w&15) + k (100..111 zero-padded)
#define PPAD 112
#define NTILES (Bn * (Ln / TL))  // 1024
#define GRID 148
#define NTHR (NW * 32)           // 1024
#define XO_OFF (32 * SROW + 16)  // Xo base: +16 words -> odd-lane STS banks disjoint

typedef unsigned long long ull;

__global__ void zero_cdf_kernel(float* out) {
    int i = blockIdx.x * 256 + threadIdx.x;
    if (i < Bn * Pn * Qn) out[i] = 0.0f;
}

__device__ __forceinline__ ull ffma2(ull a, ull b, ull c) {
    ull d;
    asm("fma.rn.f32x2 %0, %1, %2, %3;" : "=l"(d) : "l"(a), "l"(b), "l"(c));
    return d;
}
__device__ __forceinline__ ull addf2(ull a, ull b) {
    ull d;
    asm("add.rn.f32x2 %0, %1, %2;" : "=l"(d) : "l"(a), "l"(b));
    return d;
}
__device__ __forceinline__ void unpack2(ull v, float& x, float& y) {
    asm("mov.b64 {%0,%1}, %2;" : "=f"(x), "=f"(y) : "l"(v));
}
__device__ __forceinline__ void stg_cs_f2(float2* p, float x, float y) {
    asm volatile("st.global.cs.v2.f32 [%0], {%1,%2};" :: "l"(p), "f"(x), "f"(y) : "memory");
}

// item = (cc, h): warp loads c = 4cc..4cc+3 for l = 32h + lane.  item in [0,128)
__device__ __forceinline__ float4 load_item(const float* Xb, int lane, int item) {
    int cc = item >> 1, h = item & 1;
    const float* s = Xb + (size_t)(4 * cc) * Ln + 32 * h + lane;
    float4 v;
    v.x = __ldcs(s);
    v.y = __ldcs(s + Ln);
    v.z = __ldcs(s + 2 * Ln);
    v.w = __ldcs(s + 3 * Ln);
    return v;
}
// STS.128, conflict-free per 8-lane phase
__device__ __forceinline__ void stage_item(float* Xe, int lane, int item, float4 v) {
    int cc = item >> 1, h = item & 1;
    int r = 16 * h + (lane >> 1);
    float* base = Xe + ((lane & 1) ? XO_OFF : 0) + r * SROW + 4 * cc;
    *(float4*)base = v;
}

__global__ __launch_bounds__(NTHR, 1)
void csf_persistent_kernel(const float* __restrict__ X,
                           const float* __restrict__ proj,
                           const float* __restrict__ minv,
                           const float* __restrict__ maxv,
                           float* __restrict__ out) {
    extern __shared__ float sm[];
    float* Xe  = sm;                         // rows: l=2r; Xo at +XO_OFF: l=2r+1
    float* pst = sm + XO_OFF + 32 * SROW;    // [PPAD][Cn], rows >= Pn zero
    float* thr = pst + PPAD * Cn;            // [Pn*Qn]

    const int tid  = threadIdx.x;
    const int w    = tid >> 5;
    const int lane = tid & 31;
    const int pw   = w & 15;                 // pair id
    const bool hi  = (w >= 16);              // high half computes c in [128,256)
    const int coff = hi ? 128 : 0;

    // ---- One-time staging: projections (zero-pad) + thresholds ----
    {
        const int total4 = PPAD * Cn / 4;    // 7168
        const int lim4   = Pn * Cn / 4;      // 6400
        for (int i = tid; i < total4; i += NTHR) {
            float4 v = make_float4(0.f, 0.f, 0.f, 0.f);
            if (i < lim4) v = ((const float4*)proj)[i];
            ((float4*)pst)[i] = v;
        }
        for (int i = tid; i < Pn * Qn; i += NTHR) {
            int p = i / Qn, q = i % Qn;
            float f = (float)(q + 1) / (float)(Qn + 1);
            thr[i] = minv[p] + (maxv[p] - minv[p]) * f;
        }
    }

    const int pbase = KP * pw;
    const float* psb = pst + pbase * Cn + coff;
    const float* xa = Xe + lane * SROW + coff;            // l = l0 + 2*lane
    const float* xb = Xe + XO_OFF + lane * SROW + coff;   // l = l0 + 2*lane + 1

    int t = blockIdx.x;
    if (t >= NTILES) return;

    // Prologue: stage first tile (128 items = 4 rounds x 32 warps, exact).
    {
        const float* Xb = X + (size_t)(t >> 6) * Cn * Ln + (t & 63) * TL;
        #pragma unroll
        for (int j = 0; j < 4; j++)
            stage_item(Xe, lane, j * NW + w, load_item(Xb, lane, j * NW + w));
    }
    __syncthreads();

    while (true) {
        const int b  = t >> 6;
        const int l0 = (t & 63) * TL;

        // ---- Prefetch 2 of this warp's 4 next-tile items (hidden by compute) ----
        const int tn = t + GRID;
        const bool have = (tn < NTILES);
        const float* Xb2 = X + (size_t)(tn >> 6) * Cn * Ln + (tn & 63) * TL;
        float4 pf0, pf1;
        if (have) {
            pf0 = load_item(Xb2, lane, w);
            pf1 = load_item(Xb2, lane, NW + w);
        }

        // ---- Compute own c-half: pair (pw, pw+16) shares p rows & l rows ----
        ull acc0[KP], acc1[KP];
        #pragma unroll
        for (int k = 0; k < KP; k++) { acc0[k] = 0ull; acc1[k] = 0ull; }

        #pragma unroll 2
        for (int c = 0; c < 128; c += 8) {
            ulonglong2 x0a = *(const ulonglong2*)(xa + c);
            ulonglong2 x0b = *(const ulonglong2*)(xa + c + 4);
            ulonglong2 x1a = *(const ulonglong2*)(xb + c);
            ulonglong2 x1b = *(const ulonglong2*)(xb + c + 4);
            #pragma unroll
            for (int k = 0; k < KP; k++) {
                ulonglong2 pva = *(const ulonglong2*)(psb + k * Cn + c);
                ulonglong2 pvb = *(const ulonglong2*)(psb + k * Cn + c + 4);
                acc0[k] = ffma2(pva.x, x0a.x, acc0[k]);
                acc0[k] = ffma2(pva.y, x0a.y, acc0[k]);
                acc0[k] = ffma2(pvb.x, x0b.x, acc0[k]);
                acc0[k] = ffma2(pvb.y, x0b.y, acc0[k]);
                acc1[k] = ffma2(pva.x, x1a.x, acc1[k]);
                acc1[k] = ffma2(pva.y, x1a.y, acc1[k]);
                acc1[k] = ffma2(pvb.x, x1b.x, acc1[k]);
                acc1[k] = ffma2(pvb.y, x1b.y, acc1[k]);
            }
        }

        // ---- Pair reduction through (now dead) X smem as scratch ----
        __syncthreads();                 // everyone done reading X tile
        {
            ull* xch = (ull*)sm + (size_t)pw * (32 * 2 * KP);
            if (hi) {
                #pragma unroll
                for (int k = 0; k < KP; k++) {
                    xch[(2 * k) * 32 + lane]     = acc0[k];
                    xch[(2 * k + 1) * 32 + lane] = acc1[k];
                }
            }
            __syncthreads();             // partner partials visible
            if (!hi) {
                #pragma unroll
                for (int k = 0; k < KP; k++) {
                    acc0[k] = addf2(acc0[k], xch[(2 * k) * 32 + lane]);
                    acc1[k] = addf2(acc1[k], xch[(2 * k + 1) * 32 + lane]);
                }
            }
            __syncthreads();             // exchange reads done; X writable
        }

        // ---- Stage next tile: 2 prefetched + 2 direct items per warp ----
        if (have) {
            float4 d2 = load_item(Xb2, lane, 2 * NW + w);
            float4 d3 = load_item(Xb2, lane, 3 * NW + w);
            stage_item(Xe, lane, w, pf0);
            stage_item(Xe, lane, NW + w, pf1);
            stage_item(Xe, lane, 2 * NW + w, d2);
            stage_item(Xe, lane, 3 * NW + w, d3);
            __syncthreads();             // X(t+1) ready
        }

        // ---- Epilogue (low warps only) overlaps high warps' next compute ----
        if (!hi) {
            float* cdfb = out + b * (Pn * Qn);
            float* setb = out + Bn * Pn * Qn + (size_t)b * Pn * Qn * Ln;

            #pragma unroll
            for (int k = 0; k < KP; k++) {
                const int p = pbase + k;
                if (p >= Pn) break;      // uniform within warp
                float e0, o0, e1, o1;
                unpack2(acc0[k], e0, o0);
                unpack2(acc1[k], e1, o1);
                float a0 = e0 + o0;      // l = l0 + 2*lane
                float a1 = e1 + o1;      // l = l0 + 2*lane + 1

                float2* dst = (float2*)(setb + (size_t)p * Qn * Ln + l0) + lane;
                const float* th = thr + p * Qn;

                #pragma unroll
                for (int qq = 0; qq < Qn; qq += 4) {
                    unsigned packed = 0;
                    #pragma unroll
                    for (int j = 0; j < 4; j++) {
                        float tt = th[qq + j];
                        bool c0 = (a0 < tt);
                        bool c1 = (a1 < tt);
                        stg_cs_f2(dst + (size_t)(qq + j) * (Ln / 2),
                                  c0 ? 1.0f : 0.0f, c1 ? 1.0f : 0.0f);
                        packed += ((c0 ? 1u : 0u) + (c1 ? 1u : 0u)) << (8 * j);
                    }
                    unsigned r = __reduce_add_sync(0xffffffffu, packed);
                    if (lane < 4) {
                        float v = (float)((r >> (8 * lane)) & 255u) * (1.0f / 4096.0f);
                        atomicAdd(cdfb + p * Qn + qq + lane, v);   // exact dyadic
                    }
                }
            }
        }

        if (!have) break;
        t = tn;     // high warps sprint ahead into compute(t+1)
    }
}

extern "C" void kernel_launch(void* const* d_in, const int* in_sizes, int n_in,
                              void* d_out, int out_size) {
    const float* X    = (const float*)d_in[0];
    const float* proj = (const float*)d_in[1];
    const float* minv = (const float*)d_in[2];
    const float* maxv = (const float*)d_in[3];
    float* out = (float*)d_out;

    zero_cdf_kernel<<<(Bn * Pn * Qn + 255) / 256, 256>>>(out);

    const int smem = (XO_OFF + 32 * SROW + PPAD * Cn + Pn * Qn) * (int)sizeof(float);
    cudaFuncSetAttribute(csf_persistent_kernel,
                         cudaFuncAttributeMaxDynamicSharedMemorySize, smem);
    csf_persistent_kernel<<<GRID, NTHR, smem>>>(X, proj, minv, maxv, out);
}